// round 5
// baseline (speedup 1.0000x reference)
#include <cuda_runtime.h>
#include <math.h>

#define H_IMG   256
#define NUM_V   512
#define NUM_F   1024
#define TPB     256

#define NTILES  256                  // (256/16)^2 tiles of 16x16 px
#define NCHUNK  4                    // power of two (wrap-safe counters)
#define CHUNK   256                  // faces per chunk

#define LOG_EPS (-13.815511f)        // log(1e-6) = log1p(-(1-1e-6))
#define HI_T    (0.03717f)           // dist>HI  => contribution == LOG_EPS exactly
#define LO_T    (-0.0448f)           // dist<LO  => |contribution| < 2.1e-9
#define TILE_R  (0.0830f)            // pixel-center half-diagonal of 16px tile
#define SKIP_C  (LO_T - TILE_R)
#define SAT_C   (HI_T + TILE_R)

// Device scratch (no allocations anywhere). Counters never reset: NCHUNK and
// NTILES are powers of two, so (old & (N-1)) == N-1 is wrap-safe across replays.
__device__ float4   g_face[NUM_F * 3];           // per-edge (A,B,C,_) per face
__device__ float    g_S[NCHUNK * H_IMG * H_IMG]; // per-(chunk,pixel) partial S
__device__ float    g_partial[NTILES];
__device__ unsigned g_tile_cnt[NTILES];
__device__ unsigned g_done;

// ---------------------------------------------------------------------------
// K1: project all 1024 faces ONCE. 4 blocks x 256 threads. Tiny.
// ---------------------------------------------------------------------------
__global__ void __launch_bounds__(TPB)
setup_kernel(const float* __restrict__ verts,
             const int*   __restrict__ faces,
             const float* __restrict__ cam)
{
    const int f = blockIdx.x * TPB + threadIdx.x;
    if (f >= NUM_F) return;

    float ex = __ldg(&cam[0]), ey = __ldg(&cam[1]), ez = __ldg(&cam[2]);

    // camera basis (z = normalize(-eye); x = normalize(cross(up,z)); y = cross(z,x)/|.|)
    float nl = sqrtf(ex*ex + ey*ey + ez*ez) + 1e-8f;
    float rnl = 1.0f / nl;
    float zx = -ex*rnl, zy = -ey*rnl, zz = -ez*rnl;
    float cl = sqrtf(zz*zz + zx*zx) + 1e-8f;
    float rcl = 1.0f / cl;
    float xax = zz*rcl, xay = 0.0f, xaz = -zx*rcl;
    float yx = zy*xaz - zz*xay;
    float yy = zz*xax - zx*xaz;
    float yz = zx*xay - zy*xax;
    float yl = sqrtf(yx*yx + yy*yy + yz*yz) + 1e-8f;
    float ryl = 1.0f / yl;
    yx *= ryl; yy *= ryl; yz *= ryl;

    const float t = 0.57735026918962576f;   // tan(30 deg)

    float sx[3], sy[3];
    bool valid = true;
    #pragma unroll
    for (int k = 0; k < 3; k++) {
        int vi = __ldg(&faces[f*3 + k]);
        float px = __ldg(&verts[vi*3 + 0]) - ex;
        float py = __ldg(&verts[vi*3 + 1]) - ey;
        float pz = __ldg(&verts[vi*3 + 2]) - ez;
        float X = px*xax + py*xay + pz*xaz;
        float Y = px*yx  + py*yy  + pz*yz;
        float Z = px*zx  + py*zy  + pz*zz;
        valid = valid && (Z > 0.001f);
        float rden = 1.0f / (Z*t + 1e-8f);
        sx[k] = X * rden;
        sy[k] = Y * rden;
    }

    #pragma unroll
    for (int k = 0; k < 3; k++) {
        int a = k;
        int b = (k == 2) ? 0 : (k + 1);
        float eex = sx[b] - sx[a];
        float eey = sy[b] - sy[a];
        float il  = 1.0f / (sqrtf(eex*eex + eey*eey) + 1e-8f);
        float A = -eey * il;
        float B =  eex * il;
        float C = (eey * sx[a] - eex * sy[a]) * il;
        if (!valid) {                 // sentinel: dist=-1e30 -> always skipped
            A = 0.0f; B = 0.0f;
            C = (k == 2) ? 1e30f : -1e30f;
        }
        g_face[f*3 + k] = make_float4(A, B, C, 0.0f);
    }
}

__device__ __forceinline__ float face_dist(const float4 e0, const float4 e1,
                                           const float4 e2, float qx, float qy)
{
    float d0 = fmaf(e0.x, qx, fmaf(e0.y, qy, e0.z));
    float d1 = fmaf(e1.x, qx, fmaf(e1.y, qy, e1.z));
    float d2 = fmaf(e2.x, qx, fmaf(e2.y, qy, e2.z));
    float dmin = fminf(fminf(d0, d1), d2);
    float dmax = fmaxf(fmaxf(d0, d1), d2);
    return fmaxf(dmin, -dmax);
}

// ---------------------------------------------------------------------------
// K2: render + fused finish. Grid (NTILES, NCHUNK) = (256, 4).
//   B1: load 256-face chunk coeffs from L2-hot g_face (12KB smem).
//   B2: classify 1 face/thread vs tile (Lipschitz), ballot-compact per warp.
//   B3: per-pixel band loop -> g_S[chunk].
//   B4: 4th block per tile combines chunks (L2-hot), SSE -> g_partial.
//   B5: 256th tile-finisher: fixed-order 256-way tree + distance penalty.
// All FP sum orders fixed => deterministic. No spin-waits => no deadlock.
// ---------------------------------------------------------------------------
__global__ void __launch_bounds__(TPB)
render_kernel(const float* __restrict__ cam,
              const float* __restrict__ img,
              float*       __restrict__ out)
{
    __shared__ float4   sf[CHUNK * 3];   // 12 KB
    __shared__ int      slist[CHUNK];    // per-warp segments of 32
    __shared__ int      wcnt[8];
    __shared__ int      wsat[8];
    __shared__ float    red[8];
    __shared__ unsigned elect;

    const int tid  = threadIdx.x;
    const int tile = blockIdx.x;
    const int c    = blockIdx.y;
    const int w    = tid >> 5, lane = tid & 31;

    // ---- B1: coefficients from global (L2-hot) ----
    #pragma unroll
    for (int i = 0; i < 3; i++)
        sf[i * TPB + tid] = g_face[c * (CHUNK * 3) + i * TPB + tid];
    __syncthreads();

    // ---- B2: classify one face per thread ----
    const int tx = tile & 15, ty = tile >> 4;
    const float cx =  ((tx * 16 + 8.0f) / 128.0f) - 1.0f;
    const float cy = -(((ty * 16 + 8.0f) / 128.0f) - 1.0f);

    {
        float dc = face_dist(sf[3*tid], sf[3*tid+1], sf[3*tid+2], cx, cy);
        bool sat  = (dc > SAT_C);
        bool band = (dc > SKIP_C) && !sat;
        unsigned mb = __ballot_sync(0xffffffffu, band);
        unsigned ms = __ballot_sync(0xffffffffu, sat);
        if (band) {
            int pos = __popc(mb & ((1u << lane) - 1u));
            slist[w * 32 + pos] = tid;
        }
        if (lane == 0) {
            wcnt[w] = __popc(mb);
            wsat[w] = __popc(ms);
        }
    }
    __syncthreads();

    int sat_total = 0;
    #pragma unroll
    for (int i = 0; i < 8; i++) sat_total += wsat[i];

    // ---- B3: per-pixel band loop ----
    const int col = tx * 16 + (tid & 15);
    const int row = ty * 16 + (tid >> 4);
    const int pix = row * H_IMG + col;
    const float qx =  ((col + 0.5f) / 128.0f) - 1.0f;
    const float qy = -(((row + 0.5f) / 128.0f) - 1.0f);

    float S   = 0.0f;
    int   cnt = sat_total;

    #pragma unroll 1
    for (int ww = 0; ww < 8; ww++) {
        const int n = wcnt[ww];
        for (int j = 0; j < n; j++) {
            int fi = slist[ww * 32 + j];
            float dist = face_dist(sf[3*fi], sf[3*fi+1], sf[3*fi+2], qx, qy);
            if (dist > HI_T) {
                cnt++;
            } else if (dist > LO_T) {
                float x  = dist * fabsf(dist) * 1e4f;
                float ax = fabsf(x);
                float sp = ax + log1pf(__expf(-ax));     // softplus(|x|)
                float cc = (x > 0.0f) ? -sp : (ax - sp); // -softplus(x)
                S += fmaxf(cc, LOG_EPS);
            }
        }
    }

    S += (float)cnt * LOG_EPS;
    g_S[c * (H_IMG * H_IMG) + pix] = S;

    // ---- B4 election: 4th arrival for this tile combines it ----
    __threadfence();
    __syncthreads();
    if (tid == 0) elect = atomicAdd(&g_tile_cnt[tile], 1u);
    __syncthreads();
    if ((elect & (NCHUNK - 1)) != (NCHUNK - 1)) return;

    float Ssum = 0.0f;
    #pragma unroll
    for (int cc = 0; cc < NCHUNK; cc++)                   // fixed order
        Ssum += __ldcg(&g_S[cc * (H_IMG * H_IMG) + pix]); // L1-bypass (coherent)

    float alpha = 1.0f - expf(Ssum);
    float r = __ldg(&img[pix]) - alpha;
    float v = r * r;

    #pragma unroll
    for (int o = 16; o > 0; o >>= 1)
        v += __shfl_down_sync(0xffffffffu, v, o);
    if (lane == 0) red[w] = v;
    __syncthreads();

    if (tid == 0) {
        float bs = 0.0f;
        #pragma unroll
        for (int i = 0; i < 8; i++) bs += red[i];         // fixed order
        g_partial[tile] = bs;
        __threadfence();
        elect = atomicAdd(&g_done, 1u);
    }
    __syncthreads();

    // ---- B5: 256th tile-finisher does the final reduce ----
    if ((elect & (NTILES - 1)) != (NTILES - 1)) return;

    __shared__ float fred[TPB];
    fred[tid] = __ldcg(&g_partial[tid]);                  // NTILES == TPB
    __syncthreads();
    #pragma unroll
    for (int o = TPB / 2; o > 0; o >>= 1) {               // fixed-order tree
        if (tid < o) fred[tid] += fred[tid + o];
        __syncthreads();
    }
    if (tid == 0) {
        float ex = __ldg(&cam[0]), ey = __ldg(&cam[1]), ez = __ldg(&cam[2]);
        float d = sqrtf(ex*ex + ey*ey + ez*ez);
        float pen = fmaxf(0.0f, 6.0f - d);
        out[0] = fred[0] * (1.0f + pen);
    }
}

// ---------------------------------------------------------------------------
extern "C" void kernel_launch(void* const* d_in, const int* in_sizes, int n_in,
                              void* d_out, int out_size)
{
    const float* verts = nullptr;
    const int*   faces = nullptr;
    const float* img   = nullptr;
    const float* cam   = nullptr;

    for (int i = 0; i < n_in; i++) {
        switch (in_sizes[i]) {
            case NUM_V * 3:      verts = (const float*)d_in[i]; break;
            case NUM_F * 3:      faces = (const int*)  d_in[i]; break;
            case H_IMG * H_IMG:  img   = (const float*)d_in[i]; break;
            case 3:              cam   = (const float*)d_in[i]; break;
            default: break;
        }
    }

    setup_kernel<<<NUM_F / TPB, TPB>>>(verts, faces, cam);

    dim3 grid(NTILES, NCHUNK);
    render_kernel<<<grid, TPB>>>(cam, img, (float*)d_out);
}

// round 6
// speedup vs baseline: 1.6476x; 1.6476x over previous
#include <cuda_runtime.h>
#include <math.h>

#define H_IMG   256
#define NUM_V   512
#define NUM_F   1024
#define TPB     256

#define NTILES  256                  // (256/16)^2 tiles of 16x16 px
#define NCHUNK  8                    // power of two (wrap-safe counters)
#define CHUNK   128                  // faces per chunk

#define LOG_EPS (-13.815511f)        // log(1e-6)
#define HI_T    (0.0371693f)         // dist>HI  => contribution == LOG_EPS exactly
#define LO_T    (-0.0448f)           // dist<LO  => |contribution| < 2.1e-9
#define TILE_R  (0.0830f)            // pixel-center half-diagonal of 16px tile
#define SKIP_C  (LO_T - TILE_R)
#define SAT_C   (HI_T + TILE_R)

// Device scratch. Counters never reset: NTILES is a power of two, so
// (old & (NTILES-1)) == NTILES-1 is wrap-safe across graph replays.
__device__ float4   g_face[NUM_F * 3];             // per-edge (A,B,C,_) per face
__device__ float    g_S[H_IMG * H_IMG * NCHUNK];   // interleaved [pix][chunk]
__device__ float    g_partial[NTILES];
__device__ unsigned g_done;

// ---------------------------------------------------------------------------
// K1: project all 1024 faces ONCE.
// ---------------------------------------------------------------------------
__global__ void __launch_bounds__(TPB)
setup_kernel(const float* __restrict__ verts,
             const int*   __restrict__ faces,
             const float* __restrict__ cam)
{
    const int f = blockIdx.x * TPB + threadIdx.x;
    if (f >= NUM_F) return;

    float ex = __ldg(&cam[0]), ey = __ldg(&cam[1]), ez = __ldg(&cam[2]);

    // camera basis
    float rnl = 1.0f / (sqrtf(ex*ex + ey*ey + ez*ez) + 1e-8f);
    float zx = -ex*rnl, zy = -ey*rnl, zz = -ez*rnl;
    float rcl = 1.0f / (sqrtf(zz*zz + zx*zx) + 1e-8f);
    float xax = zz*rcl, xay = 0.0f, xaz = -zx*rcl;  // normalize(cross(up,z))
    float yx = zy*xaz - zz*xay;
    float yy = zz*xax - zx*xaz;
    float yz = zx*xay - zy*xax;
    float ryl = 1.0f / (sqrtf(yx*yx + yy*yy + yz*yz) + 1e-8f);
    yx *= ryl; yy *= ryl; yz *= ryl;

    const float t = 0.57735026918962576f;   // tan(30 deg)

    float sx[3], sy[3];
    bool valid = true;
    #pragma unroll
    for (int k = 0; k < 3; k++) {
        int vi = __ldg(&faces[f*3 + k]);
        float px = __ldg(&verts[vi*3 + 0]) - ex;
        float py = __ldg(&verts[vi*3 + 1]) - ey;
        float pz = __ldg(&verts[vi*3 + 2]) - ez;
        float X = px*xax + py*xay + pz*xaz;
        float Y = px*yx  + py*yy  + pz*yz;
        float Z = px*zx  + py*zy  + pz*zz;
        valid = valid && (Z > 0.001f);
        float rden = 1.0f / (Z*t + 1e-8f);
        sx[k] = X * rden;
        sy[k] = Y * rden;
    }

    #pragma unroll
    for (int k = 0; k < 3; k++) {
        int a = k;
        int b = (k == 2) ? 0 : (k + 1);
        float eex = sx[b] - sx[a];
        float eey = sy[b] - sy[a];
        float il  = 1.0f / (sqrtf(eex*eex + eey*eey) + 1e-8f);
        float A = -eey * il;
        float B =  eex * il;
        float C = (eey * sx[a] - eex * sy[a]) * il;
        if (!valid) {                 // sentinel: dist=-1e30 -> always skipped
            A = 0.0f; B = 0.0f;
            C = (k == 2) ? 1e30f : -1e30f;
        }
        g_face[f*3 + k] = make_float4(A, B, C, 0.0f);
    }
}

__device__ __forceinline__ float face_dist(const float4 e0, const float4 e1,
                                           const float4 e2, float qx, float qy)
{
    float d0 = fmaf(e0.x, qx, fmaf(e0.y, qy, e0.z));
    float d1 = fmaf(e1.x, qx, fmaf(e1.y, qy, e1.z));
    float d2 = fmaf(e2.x, qx, fmaf(e2.y, qy, e2.z));
    float dmin = fminf(fminf(d0, d1), d2);
    float dmax = fmaxf(fmaxf(d0, d1), d2);
    return fmaxf(dmin, -dmax);
}

// ---------------------------------------------------------------------------
// K2: render. Grid (NTILES, NCHUNK) = (256, 8). No fences, no elections.
//   - classify this chunk's 128 faces straight from L2-hot g_face
//   - compact ONLY band faces into smem (deterministic warp-prefix bases)
//   - uniform per-pixel loop over the compacted list (broadcast LDS)
//   - write per-(pixel,chunk) S interleaved for vector-load combine
// ---------------------------------------------------------------------------
__global__ void __launch_bounds__(TPB)
render_kernel()
{
    __shared__ float4 sband[CHUNK * 3];   // compacted band faces (worst case 6KB)
    __shared__ int    wcnt[4];
    __shared__ int    wsat[4];

    const int tid  = threadIdx.x;
    const int tile = blockIdx.x;
    const int c    = blockIdx.y;
    const int w    = tid >> 5, lane = tid & 31;

    const int tx = tile & 15, ty = tile >> 4;
    const float cx =  ((tx * 16 + 8.0f) / 128.0f) - 1.0f;
    const float cy = -(((ty * 16 + 8.0f) / 128.0f) - 1.0f);

    // ---- classify 1 face/thread (threads 0..127), compact band faces ----
    float4 e0, e1, e2;
    unsigned mb = 0u;
    int pos = 0;
    if (tid < CHUNK) {
        const int gf = (c * CHUNK + tid) * 3;
        e0 = g_face[gf + 0];
        e1 = g_face[gf + 1];
        e2 = g_face[gf + 2];
        float dc = face_dist(e0, e1, e2, cx, cy);
        bool sat  = (dc > SAT_C);
        bool band = (dc > SKIP_C) && !sat;
        mb          = __ballot_sync(0xffffffffu, band);
        unsigned ms = __ballot_sync(0xffffffffu, sat);
        pos = __popc(mb & ((1u << lane) - 1u));
        if (lane == 0) {
            wcnt[w] = __popc(mb);
            wsat[w] = __popc(ms);
        }
        if (!band) mb = 0u;   // reuse mb as "I am band" flag via lane bit
        else       mb = 1u;
    }
    __syncthreads();

    // deterministic per-warp bases (exclusive prefix of wcnt[0..3])
    int base0 = 0;
    int base1 = wcnt[0];
    int base2 = base1 + wcnt[1];
    int base3 = base2 + wcnt[2];
    const int n_total   = base3 + wcnt[3];
    const int sat_total = wsat[0] + wsat[1] + wsat[2] + wsat[3];

    if (tid < CHUNK && mb) {
        int base = (w == 0) ? base0 : (w == 1) ? base1 : (w == 2) ? base2 : base3;
        int s = base + pos;
        sband[3*s + 0] = e0;
        sband[3*s + 1] = e1;
        sband[3*s + 2] = e2;
    }
    __syncthreads();

    // ---- per-pixel loop over compacted band list (uniform bounds) ----
    const int col = tx * 16 + (tid & 15);
    const int row = ty * 16 + (tid >> 4);
    const int pix = row * H_IMG + col;
    const float qx =  ((col + 0.5f) / 128.0f) - 1.0f;
    const float qy = -(((row + 0.5f) / 128.0f) - 1.0f);

    float S   = 0.0f;
    int   cnt = sat_total;

    for (int j = 0; j < n_total; j++) {
        float dist = face_dist(sband[3*j], sband[3*j+1], sband[3*j+2], qx, qy);
        if (dist > HI_T) {
            cnt++;
        } else if (dist > LO_T) {
            // -softplus(x) via fast MUFU path; |err| ~1e-6 << tolerance
            float x = dist * fabsf(dist) * 1e4f;
            float cc = -__logf(fmaf(__expf(x), 1.0f, 1.0f));
            S += fmaxf(cc, LOG_EPS);
        }
    }

    S += (float)cnt * LOG_EPS;
    g_S[pix * NCHUNK + c] = S;     // interleaved: combine reads 2x float4
}

// ---------------------------------------------------------------------------
// K3: combine + finish (last-block election; fixed-order sums).
// ---------------------------------------------------------------------------
__global__ void __launch_bounds__(TPB)
combine_kernel(const float* __restrict__ img,
               const float* __restrict__ cam,
               float*       __restrict__ out)
{
    __shared__ float    red[8];
    __shared__ unsigned elect;

    const int tid = threadIdx.x;
    const int w   = tid >> 5, lane = tid & 31;
    const int pix = blockIdx.x * TPB + tid;

    const float4* p = (const float4*)&g_S[pix * NCHUNK];
    float4 a = p[0];
    float4 b = p[1];
    float S = ((a.x + a.y) + (a.z + a.w)) + ((b.x + b.y) + (b.z + b.w));

    float alpha = 1.0f - expf(S);
    float r = __ldg(&img[pix]) - alpha;
    float v = r * r;

    #pragma unroll
    for (int o = 16; o > 0; o >>= 1)
        v += __shfl_down_sync(0xffffffffu, v, o);
    if (lane == 0) red[w] = v;
    __syncthreads();

    if (tid == 0) {
        float bs = 0.0f;
        #pragma unroll
        for (int i = 0; i < 8; i++) bs += red[i];      // fixed order
        g_partial[blockIdx.x] = bs;
        __threadfence();
        elect = atomicAdd(&g_done, 1u);
    }
    __syncthreads();

    if ((elect & (NTILES - 1)) != (NTILES - 1)) return;   // wrap-safe

    __shared__ float fred[TPB];
    fred[tid] = __ldcg(&g_partial[tid]);                  // NTILES == TPB
    __syncthreads();
    #pragma unroll
    for (int o = TPB / 2; o > 0; o >>= 1) {               // fixed-order tree
        if (tid < o) fred[tid] += fred[tid + o];
        __syncthreads();
    }
    if (tid == 0) {
        float ex = __ldg(&cam[0]), ey = __ldg(&cam[1]), ez = __ldg(&cam[2]);
        float d = sqrtf(ex*ex + ey*ey + ez*ez);
        float pen = fmaxf(0.0f, 6.0f - d);
        out[0] = fred[0] * (1.0f + pen);
    }
}

// ---------------------------------------------------------------------------
extern "C" void kernel_launch(void* const* d_in, const int* in_sizes, int n_in,
                              void* d_out, int out_size)
{
    const float* verts = nullptr;
    const int*   faces = nullptr;
    const float* img   = nullptr;
    const float* cam   = nullptr;

    for (int i = 0; i < n_in; i++) {
        switch (in_sizes[i]) {
            case NUM_V * 3:      verts = (const float*)d_in[i]; break;
            case NUM_F * 3:      faces = (const int*)  d_in[i]; break;
            case H_IMG * H_IMG:  img   = (const float*)d_in[i]; break;
            case 3:              cam   = (const float*)d_in[i]; break;
            default: break;
        }
    }

    setup_kernel<<<NUM_F / TPB, TPB>>>(verts, faces, cam);

    dim3 grid(NTILES, NCHUNK);
    render_kernel<<<grid, TPB>>>();

    combine_kernel<<<(H_IMG * H_IMG) / TPB, TPB>>>(img, cam, (float*)d_out);
}